// round 1
// baseline (speedup 1.0000x reference)
#include <cuda_runtime.h>
#include <cuda_bf16.h>
#include <cstddef>

// Problem constants
#define B_    4
#define CI_   256
#define CO_   256
#define H_    64
#define W_    64
#define HW_   4096          // 64*64
#define KK_   9             // 3x3
#define KDIM  (CI_ * KK_)   // 2304

// Column buffer: col[b][k][p], k = ci*9 + kk  (matches weight[co][ci][i][j] flattening)
// 4 * 2304 * 4096 * 4 B = 151 MB, static device allocation (allowed).
__device__ float g_col[(size_t)B_ * KDIM * HW_];

// ---------------------------------------------------------------------------
// Kernel 1: bilinear im2col.
// One thread per (b, kk, pixel). Corner indices/weights computed once,
// then a 256-iteration channel loop: 4 gather loads + 1 coalesced store.
// Grid: B*9*16 blocks of 256 threads (16 blocks cover the 4096 pixels).
// ---------------------------------------------------------------------------
__global__ __launch_bounds__(256) void im2col_kernel(
    const float* __restrict__ x,       // [B, CI, 64, 64]
    const float* __restrict__ offset)  // [B, 18, 64, 64]
{
    int blk  = blockIdx.x;
    int tile = blk & 15;          // 0..15
    int kk   = (blk >> 4) % KK_;  // 0..8
    int b    = blk / (16 * KK_);  // 0..3

    int p = tile * 256 + threadIdx.x;   // 0..4095
    int h = p >> 6;
    int w = p & 63;
    int i = kk / 3;
    int j = kk % 3;

    const float* offb = offset + (size_t)b * 18 * HW_;
    float offy = offb[(size_t)(2 * kk)     * HW_ + p];
    float offx = offb[(size_t)(2 * kk + 1) * HW_ + p];

    // Padded-coordinate sample point: py = (h+1) + (i-1) + offy = h + i + offy
    float py = (float)(h + i) + offy;
    float px = (float)(w + j) + offx;

    float y0f = floorf(py);
    float x0f = floorf(px);
    float ly = py - y0f;
    float lx = px - x0f;
    int y0 = (int)y0f - 1;   // unpadded coords
    int x0 = (int)x0f - 1;

    float wts[4] = { (1.f - ly) * (1.f - lx),
                     (1.f - ly) * lx,
                     ly * (1.f - lx),
                     ly * lx };
    int idx[4];
    #pragma unroll
    for (int c = 0; c < 4; c++) {
        int yi = y0 + (c >> 1);
        int xi = x0 + (c & 1);
        bool v = (yi >= 0) & (yi < H_) & (xi >= 0) & (xi < W_);
        idx[c] = v ? (yi * W_ + xi) : 0;
        if (!v) wts[c] = 0.f;
    }

    const float* xb = x + (size_t)b * CI_ * HW_;
    float* colp = g_col + ((size_t)b * KDIM + kk) * HW_ + p;

    #pragma unroll 4
    for (int ci = 0; ci < CI_; ci++) {
        const float* xc = xb + (size_t)ci * HW_;
        float v = wts[0] * xc[idx[0]] + wts[1] * xc[idx[1]]
                + wts[2] * xc[idx[2]] + wts[3] * xc[idx[3]];
        colp[(size_t)ci * KK_ * HW_] = v;   // stride 9*4096 across ci; coalesced across p
    }
}

// ---------------------------------------------------------------------------
// Kernel 2: batched SGEMM  out[b][m][p] = sum_k W[m][k] * col[b][k][p]
// M=256, N=4096, K=2304. Tile 128x64x8, 256 threads, 8x4 per-thread tile.
// Grid: (N/64=64, M/128=2, B=4) = 512 blocks.
// ---------------------------------------------------------------------------
#define BM 128
#define BN 64
#define BK 8

__global__ __launch_bounds__(256) void gemm_kernel(
    const float* __restrict__ Wt,   // [CO, KDIM] row-major
    float* __restrict__ out)        // [B, CO, HW]
{
    int b  = blockIdx.z;
    int m0 = blockIdx.y * BM;
    int n0 = blockIdx.x * BN;

    const float* Bmat = g_col + (size_t)b * KDIM * HW_;
    float* C = out + (size_t)b * CO_ * HW_;

    __shared__ float As[BK][BM];
    __shared__ float Bs[BK][BN];

    int tid = threadIdx.x;

    // A tile load: 128x8 floats, one float4 per thread
    int aRow = tid >> 1;            // 0..127
    int aCol = (tid & 1) * 4;       // 0 or 4
    // B tile load: 8x64 floats, one float2 per thread
    int bRow = tid >> 5;            // 0..7
    int bCol = (tid & 31) * 2;      // 0..62

    // Per-thread output tile: 8 rows x 4 cols
    int tm = (tid >> 4) * 8;        // 0,8,...,120
    int tn = (tid & 15) * 4;        // 0,4,...,60

    float acc[8][4] = {};

    for (int k0 = 0; k0 < KDIM; k0 += BK) {
        float4 a4 = *(const float4*)(Wt + (size_t)(m0 + aRow) * KDIM + k0 + aCol);
        As[aCol + 0][aRow] = a4.x;
        As[aCol + 1][aRow] = a4.y;
        As[aCol + 2][aRow] = a4.z;
        As[aCol + 3][aRow] = a4.w;

        float2 b2 = *(const float2*)(Bmat + (size_t)(k0 + bRow) * HW_ + n0 + bCol);
        Bs[bRow][bCol + 0] = b2.x;
        Bs[bRow][bCol + 1] = b2.y;

        __syncthreads();

        #pragma unroll
        for (int kk2 = 0; kk2 < BK; kk2++) {
            float4 ra0 = *(const float4*)&As[kk2][tm];
            float4 ra1 = *(const float4*)&As[kk2][tm + 4];
            float4 rb  = *(const float4*)&Bs[kk2][tn];
            float ra[8] = { ra0.x, ra0.y, ra0.z, ra0.w, ra1.x, ra1.y, ra1.z, ra1.w };
            float rbv[4] = { rb.x, rb.y, rb.z, rb.w };
            #pragma unroll
            for (int ii = 0; ii < 8; ii++)
                #pragma unroll
                for (int jj = 0; jj < 4; jj++)
                    acc[ii][jj] += ra[ii] * rbv[jj];
        }
        __syncthreads();
    }

    #pragma unroll
    for (int ii = 0; ii < 8; ii++) {
        float4 v = make_float4(acc[ii][0], acc[ii][1], acc[ii][2], acc[ii][3]);
        *(float4*)(C + (size_t)(m0 + tm + ii) * HW_ + n0 + tn) = v;
    }
}

// ---------------------------------------------------------------------------
extern "C" void kernel_launch(void* const* d_in, const int* in_sizes, int n_in,
                              void* d_out, int out_size)
{
    const float* x   = (const float*)d_in[0];   // [4,256,64,64]
    const float* off = (const float*)d_in[1];   // [4,18,64,64]
    const float* wt  = (const float*)d_in[2];   // [256,256,3,3]
    float* out = (float*)d_out;                 // [4,256,64,64]

    im2col_kernel<<<B_ * KK_ * 16, 256>>>(x, off);

    dim3 grid(HW_ / BN, CO_ / BM, B_);
    gemm_kernel<<<grid, 256>>>(wt, out);
}

// round 4
// speedup vs baseline: 4.2570x; 4.2570x over previous
#include <cuda_runtime.h>
#include <cuda_fp16.h>
#include <cstdint>
#include <cstddef>

// Problem constants
#define B_    4
#define CI_   256
#define CO_   256
#define H_    64
#define W_    64
#define HW_   4096
#define KK_   9
#define KDIM  2304          // CI_*KK_

// fp16 column buffer: col[(b*4096+p)][k'] with k' = kk*256 + ci  (K-major rows)
__device__ __half g_col[(size_t)B_ * HW_ * KDIM];   // 75.5 MB
// fp16 repacked weight: w[co][k'] with k' = kk*256 + ci
__device__ __half g_w[(size_t)CO_ * KDIM];          // 1.2 MB

// ---------------------------------------------------------------------------
// Helpers
// ---------------------------------------------------------------------------
__device__ __forceinline__ uint32_t smem_u32(const void* p) {
    uint32_t a;
    asm("{ .reg .u64 t; cvta.to.shared.u64 t, %1; cvt.u32.u64 %0, t; }" : "=r"(a) : "l"(p));
    return a;
}
__device__ __forceinline__ void cp_async16(uint32_t dst, const void* src) {
    asm volatile("cp.async.cg.shared.global [%0], [%1], 16;" :: "r"(dst), "l"(src));
}
#define CP_COMMIT() asm volatile("cp.async.commit_group;" ::: "memory")
#define CP_WAIT2()  asm volatile("cp.async.wait_group 2;" ::: "memory")

__device__ __forceinline__ void ldsm4(uint32_t& r0, uint32_t& r1, uint32_t& r2,
                                      uint32_t& r3, uint32_t addr) {
    asm volatile("ldmatrix.sync.aligned.m8n8.x4.shared.b16 {%0,%1,%2,%3}, [%4];"
                 : "=r"(r0), "=r"(r1), "=r"(r2), "=r"(r3) : "r"(addr));
}
__device__ __forceinline__ void mma16816(float* c, const uint32_t* a, const uint32_t* b) {
    asm volatile(
        "mma.sync.aligned.m16n8k16.row.col.f32.f16.f16.f32 "
        "{%0,%1,%2,%3}, {%4,%5,%6,%7}, {%8,%9}, {%0,%1,%2,%3};"
        : "+f"(c[0]), "+f"(c[1]), "+f"(c[2]), "+f"(c[3])
        : "r"(a[0]), "r"(a[1]), "r"(a[2]), "r"(a[3]), "r"(b[0]), "r"(b[1]));
}

// ---------------------------------------------------------------------------
// Kernel 1: weight repack  g_w[co][kk*256+ci] = (half) W[co][ci][kk]
// ---------------------------------------------------------------------------
__global__ __launch_bounds__(256) void repack_w_kernel(const float* __restrict__ w) {
    int ck = blockIdx.x;            // co*9 + kk
    int ci = threadIdx.x;
    int co = ck / KK_, kk = ck % KK_;
    g_w[(size_t)ck * CI_ + ci] = __float2half(w[((size_t)co * CI_ + ci) * KK_ + kk]);
}

// ---------------------------------------------------------------------------
// Kernel 2: bilinear im2col -> fp16 col[(b*4096+p)][kk*256+ci]
// ---------------------------------------------------------------------------
__global__ __launch_bounds__(256) void im2col16_kernel(
    const float* __restrict__ x, const float* __restrict__ offset)
{
    int blk  = blockIdx.x;
    int tile = blk & 15;
    int kk   = (blk >> 4) % KK_;
    int b    = blk / (16 * KK_);

    int p = tile * 256 + threadIdx.x;
    int h = p >> 6;
    int w = p & 63;
    int i = kk / 3;
    int j = kk % 3;

    const float* offb = offset + (size_t)b * 18 * HW_;
    float offy = offb[(size_t)(2 * kk)     * HW_ + p];
    float offx = offb[(size_t)(2 * kk + 1) * HW_ + p];

    float py = (float)(h + i) + offy;       // padded coords
    float px = (float)(w + j) + offx;

    float y0f = floorf(py), x0f = floorf(px);
    float ly = py - y0f, lx = px - x0f;
    int y0 = (int)y0f - 1;                  // unpadded
    int x0 = (int)x0f - 1;

    float wts[4] = { (1.f - ly) * (1.f - lx), (1.f - ly) * lx,
                     ly * (1.f - lx),          ly * lx };
    int idx[4];
    #pragma unroll
    for (int c = 0; c < 4; c++) {
        int yi = y0 + (c >> 1), xi = x0 + (c & 1);
        bool v = (yi >= 0) & (yi < H_) & (xi >= 0) & (xi < W_);
        idx[c] = v ? (yi * W_ + xi) : 0;
        if (!v) wts[c] = 0.f;
    }

    const float* xb = x + (size_t)b * CI_ * HW_;
    __half* dst = g_col + ((size_t)(b * HW_ + p)) * KDIM + kk * 256;

    for (int ci0 = 0; ci0 < CI_; ci0 += 8) {
        uint32_t pk[4];
        #pragma unroll
        for (int u = 0; u < 4; u++) {
            const float* xa = xb + (size_t)(ci0 + 2 * u) * HW_;
            const float* xc = xa + HW_;
            float v0 = wts[0] * xa[idx[0]] + wts[1] * xa[idx[1]]
                     + wts[2] * xa[idx[2]] + wts[3] * xa[idx[3]];
            float v1 = wts[0] * xc[idx[0]] + wts[1] * xc[idx[1]]
                     + wts[2] * xc[idx[2]] + wts[3] * xc[idx[3]];
            __half2 hh = __floats2half2_rn(v0, v1);
            pk[u] = *(uint32_t*)&hh;
        }
        *(uint4*)(dst + ci0) = make_uint4(pk[0], pk[1], pk[2], pk[3]);
    }
}

// ---------------------------------------------------------------------------
// Kernel 3: HMMA GEMM  out[b][co][p] = sum_k col[p][k] * w[co][k]
// CTA tile 128x128x32, 8 warps (2x4) each 64x32, 4-stage cp.async pipeline.
// Smem layout per stage: A 128x32 half then B 128x32 half; rows of 64B with
// 16B-chunk swizzle: phys_chunk = chunk ^ ((row>>1)&3)  (conflict-free LDSM).
// ---------------------------------------------------------------------------
#define BM 128
#define BN 128
#define BK 32
#define STG 4
#define NITER (KDIM / BK)          // 72
#define STAGE_BYTES 16384          // 8KB A + 8KB B
#define SM_TOTAL (STG * STAGE_BYTES)

__global__ __launch_bounds__(256, 2) void gemm_hmma_kernel(float* __restrict__ out) {
    extern __shared__ char smem[];
    uint32_t sb = smem_u32(smem);
    int tid = threadIdx.x, wid = tid >> 5, l = tid & 31;
    int pt = blockIdx.x;            // pixel tile (0..31)
    int nt = blockIdx.y;            // co tile (0..1)
    int b  = blockIdx.z;

    int wm = wid >> 2;              // 0..1  -> 64-row slab
    int wn = wid & 3;               // 0..3  -> 32-col slab

    const __half* Abase = g_col + ((size_t)(b * HW_ + pt * BM)) * KDIM;
    const __half* Bbase = g_w + (size_t)(nt * BN) * KDIM;

    auto load_stage = [&](int c) {
        uint32_t sa = sb + (c & 3) * STAGE_BYTES;
        uint32_t sw = sa + 8192;
        int k0 = c * BK;
        #pragma unroll
        for (int t = tid; t < 512; t += 256) {
            int r = t >> 2, ch = t & 3;
            uint32_t off = r * 64 + ((ch ^ ((r >> 1) & 3)) << 4);
            cp_async16(sa + off, Abase + (size_t)r * KDIM + k0 + ch * 8);
            cp_async16(sw + off, Bbase + (size_t)r * KDIM + k0 + ch * 8);
        }
    };

    float acc[4][4][4];
    #pragma unroll
    for (int a = 0; a < 4; a++)
        #pragma unroll
        for (int bb = 0; bb < 4; bb++)
            #pragma unroll
            for (int cc = 0; cc < 4; cc++) acc[a][bb][cc] = 0.f;

    // ldmatrix lane patterns
    int laneA_r = l & 15;                       // row within m16 tile
    int laneA_c = l >> 4;                       // k-chunk select (0/1)
    int laneB_r = (l & 7) + ((l >> 4) << 3);    // row within 16-n group
    int laneB_c = (l >> 3) & 1;                 // k-chunk select

    // prologue: stages 0..2
    load_stage(0); CP_COMMIT();
    load_stage(1); CP_COMMIT();
    load_stage(2); CP_COMMIT();

    for (int c = 0; c < NITER; c++) {
        CP_WAIT2();                 // group c complete
        __syncthreads();

        uint32_t sa = sb + (c & 3) * STAGE_BYTES;
        uint32_t sw = sa + 8192;

        #pragma unroll
        for (int s = 0; s < 2; s++) {           // two k16 steps per BK=32
            uint32_t af[4][4];
            #pragma unroll
            for (int mi = 0; mi < 4; mi++) {
                int r = wm * 64 + mi * 16 + laneA_r;
                int ch = 2 * s + laneA_c;
                ldsm4(af[mi][0], af[mi][1], af[mi][2], af[mi][3],
                      sa + r * 64 + ((ch ^ ((r >> 1) & 3)) << 4));
            }
            uint32_t bf[4][2];
            #pragma unroll
            for (int nj = 0; nj < 2; nj++) {    // each x4 covers two n8 tiles
                int r = wn * 32 + nj * 16 + laneB_r;
                int ch = 2 * s + laneB_c;
                uint32_t r0, r1, r2, r3;
                ldsm4(r0, r1, r2, r3,
                      sw + r * 64 + ((ch ^ ((r >> 1) & 3)) << 4));
                bf[nj * 2][0] = r0;  bf[nj * 2][1] = r1;
                bf[nj * 2 + 1][0] = r2;  bf[nj * 2 + 1][1] = r3;
            }
            #pragma unroll
            for (int mi = 0; mi < 4; mi++)
                #pragma unroll
                for (int ni = 0; ni < 4; ni++)
                    mma16816(acc[mi][ni], af[mi], bf[ni]);
        }

        __syncthreads();
        if (c + 3 < NITER) load_stage(c + 3);
        CP_COMMIT();
    }

    // epilogue: acc[m][n] -> out[b][nt*128 + n][pt*128 + m]
    float* ob = out + ((size_t)b * CO_ + (size_t)nt * BN) * HW_ + (size_t)pt * BM;
    int mrow = wm * 64 + (l >> 2);
    int ncol = wn * 32 + ((l & 3) << 1);
    #pragma unroll
    for (int mi = 0; mi < 4; mi++) {
        #pragma unroll
        for (int ni = 0; ni < 4; ni++) {
            int m = mrow + mi * 16;
            int n = ncol + ni * 8;
            ob[(size_t)n * HW_ + m]           = acc[mi][ni][0];
            ob[(size_t)(n + 1) * HW_ + m]     = acc[mi][ni][1];
            ob[(size_t)n * HW_ + m + 8]       = acc[mi][ni][2];
            ob[(size_t)(n + 1) * HW_ + m + 8] = acc[mi][ni][3];
        }
    }
}

// ---------------------------------------------------------------------------
extern "C" void kernel_launch(void* const* d_in, const int* in_sizes, int n_in,
                              void* d_out, int out_size)
{
    const float* x   = (const float*)d_in[0];   // [4,256,64,64]
    const float* off = (const float*)d_in[1];   // [4,18,64,64]
    const float* wt  = (const float*)d_in[2];   // [256,256,3,3]
    float* out = (float*)d_out;                 // [4,256,64,64]

    cudaFuncSetAttribute(gemm_hmma_kernel,
                         cudaFuncAttributeMaxDynamicSharedMemorySize, SM_TOTAL);

    repack_w_kernel<<<CO_ * KK_, 256>>>(wt);
    im2col16_kernel<<<B_ * KK_ * 16, 256>>>(x, off);

    dim3 grid(HW_ / BM, CO_ / BN, B_);          // 32 x 2 x 4 = 256 CTAs
    gemm_hmma_kernel<<<grid, 256, SM_TOTAL>>>(out);
}

// round 5
// speedup vs baseline: 4.8636x; 1.1425x over previous
#include <cuda_runtime.h>
#include <cuda_fp16.h>
#include <cstdint>
#include <cstddef>

// Problem constants
#define B_    4
#define CI_   256
#define CO_   256
#define H_    64
#define W_    64
#define HW_   4096
#define KK_   9
#define KDIM  2304          // CI_*KK_

// channel-last input: xT[(b*4096 + hw)*256 + ci]
__device__ float g_xT[(size_t)B_ * HW_ * CI_];      // 16.8 MB
// fp16 repacked weight: w[co][k'] with k' = kk*256 + ci
__device__ __half g_w[(size_t)CO_ * KDIM];          // 1.2 MB

// ---------------------------------------------------------------------------
// Helpers
// ---------------------------------------------------------------------------
__device__ __forceinline__ uint32_t smem_u32(const void* p) {
    uint32_t a;
    asm("{ .reg .u64 t; cvta.to.shared.u64 t, %1; cvt.u32.u64 %0, t; }" : "=r"(a) : "l"(p));
    return a;
}
__device__ __forceinline__ void cp_async16(uint32_t dst, const void* src) {
    asm volatile("cp.async.cg.shared.global [%0], [%1], 16;" :: "r"(dst), "l"(src));
}
#define CP_COMMIT() asm volatile("cp.async.commit_group;" ::: "memory")
#define CP_WAIT0()  asm volatile("cp.async.wait_group 0;" ::: "memory")

__device__ __forceinline__ void ldsm4(uint32_t& r0, uint32_t& r1, uint32_t& r2,
                                      uint32_t& r3, uint32_t addr) {
    asm volatile("ldmatrix.sync.aligned.m8n8.x4.shared.b16 {%0,%1,%2,%3}, [%4];"
                 : "=r"(r0), "=r"(r1), "=r"(r2), "=r"(r3) : "r"(addr));
}
__device__ __forceinline__ void mma16816(float* c, const uint32_t* a, const uint32_t* b) {
    asm volatile(
        "mma.sync.aligned.m16n8k16.row.col.f32.f16.f16.f32 "
        "{%0,%1,%2,%3}, {%4,%5,%6,%7}, {%8,%9}, {%0,%1,%2,%3};"
        : "+f"(c[0]), "+f"(c[1]), "+f"(c[2]), "+f"(c[3])
        : "r"(a[0]), "r"(a[1]), "r"(a[2]), "r"(a[3]), "r"(b[0]), "r"(b[1]));
}
__device__ __forceinline__ void sts32(uint32_t addr, uint32_t v) {
    asm volatile("st.shared.b32 [%0], %1;" :: "r"(addr), "r"(v) : "memory");
}

// ---------------------------------------------------------------------------
// Kernel 1: tiled transpose  x[b][ci][hw] -> g_xT[b][hw][ci]
// ---------------------------------------------------------------------------
__global__ __launch_bounds__(256) void transpose_kernel(const float* __restrict__ x) {
    __shared__ float sm[32][33];
    int hw0 = blockIdx.x * 32;
    int ci0 = blockIdx.y * 32;
    int b   = blockIdx.z;
    int tx = threadIdx.x, ty = threadIdx.y;   // (32, 8)

    const float* xb = x + (size_t)b * CI_ * HW_;
    #pragma unroll
    for (int i = 0; i < 4; i++)
        sm[ty + i * 8][tx] = xb[(size_t)(ci0 + ty + i * 8) * HW_ + hw0 + tx];
    __syncthreads();
    float* xtb = g_xT + (size_t)b * HW_ * CI_;
    #pragma unroll
    for (int i = 0; i < 4; i++)
        xtb[(size_t)(hw0 + ty + i * 8) * CI_ + ci0 + tx] = sm[tx][ty + i * 8];
}

// ---------------------------------------------------------------------------
// Kernel 2: weight repack  g_w[co][kk*256+ci] = (half) W[co][ci][kk]
// ---------------------------------------------------------------------------
__global__ __launch_bounds__(256) void repack_w_kernel(const float* __restrict__ w) {
    int ck = blockIdx.x;            // co*9 + kk
    int ci = threadIdx.x;
    int co = ck / KK_, kk = ck % KK_;
    g_w[(size_t)ck * CI_ + ci] = __float2half(w[((size_t)co * CI_ + ci) * KK_ + kk]);
}

// ---------------------------------------------------------------------------
// Kernel 3: fused deformable im2col + HMMA GEMM
// CTA: 128 px x 256 co, 512 threads (16 warps, 2x8), K in 72 chunks of 32.
// Double-buffered A (gathered in-kernel) and B (cp.async from g_w).
// Smem rows 64B, swizzle phys_chunk = ch ^ ((row>>1)&3)  (same as verified R4).
// ---------------------------------------------------------------------------
#define BK 32
#define NCH (KDIM / BK)       // 72
#define SM_A0   0             // 2 x 8192  (A: 128 x 32 half)
#define SM_B0   16384         // 2 x 16384 (B: 256 x 32 half)
#define SM_IDX  49152         // int4  [16][8]
#define SM_WTS  51200         // float4[16][8]
#define SM_TOTAL 53248

__global__ __launch_bounds__(512, 1) void fused_kernel(
    const float* __restrict__ offset, float* __restrict__ out)
{
    extern __shared__ char smem[];
    uint32_t sb = smem_u32(smem);
    int tid = threadIdx.x, wid = tid >> 5, l = tid & 31;
    int pt = blockIdx.x;      // pixel tile 0..31
    int b  = blockIdx.y;

    int4*   idx_sm = (int4*)(smem + SM_IDX)  + wid * 8;
    float4* wts_sm = (float4*)(smem + SM_WTS) + wid * 8;

    const float* offb = offset + (size_t)b * 18 * HW_;
    const float* xTb  = g_xT + (size_t)b * HW_ * CI_;

    // recompute bilinear corner offsets/weights for this warp's 8 pixels at kk
    auto calc_off = [&](int kk) {
        if (l < 8) {
            int pg = pt * 128 + wid * 8 + l;
            int h = pg >> 6, w = pg & 63;
            float offy = offb[(size_t)(2 * kk)     * HW_ + pg];
            float offx = offb[(size_t)(2 * kk + 1) * HW_ + pg];
            int i = kk / 3, j = kk % 3;
            float py = (float)(h + i) + offy;   // padded coords
            float px = (float)(w + j) + offx;
            float y0f = floorf(py), x0f = floorf(px);
            float ly = py - y0f, lx = px - x0f;
            int y0 = (int)y0f - 1, x0 = (int)x0f - 1;   // unpadded
            float wt[4] = { (1.f - ly) * (1.f - lx), (1.f - ly) * lx,
                            ly * (1.f - lx),          ly * lx };
            int fl[4];
            #pragma unroll
            for (int c = 0; c < 4; c++) {
                int yi = y0 + (c >> 1), xi = x0 + (c & 1);
                bool v = (yi >= 0) & (yi < H_) & (xi >= 0) & (xi < W_);
                fl[c] = v ? (yi * W_ + xi) * CI_ : 0;
                if (!v) wt[c] = 0.f;
            }
            idx_sm[l] = make_int4(fl[0], fl[1], fl[2], fl[3]);
            wts_sm[l] = make_float4(wt[0], wt[1], wt[2], wt[3]);
        }
        __syncwarp();
    };

    float acc[4][4][4];
    #pragma unroll
    for (int a = 0; a < 4; a++)
        #pragma unroll
        for (int bb = 0; bb < 4; bb++)
            #pragma unroll
            for (int cc = 0; cc < 4; cc++) acc[a][bb][cc] = 0.f;

    // MMA warp layout (2 x 8): warp tile 64 px x 32 co
    int wm = wid >> 3;        // 0..1
    int wn = wid & 7;         // 0..7
    int laneA_r = l & 15;
    int laneA_c = l >> 4;
    int laneB_r = (l & 7) + ((l >> 4) << 3);
    int laneB_c = (l >> 3) & 1;

    float cv[8][4];           // gathered corners: 8 px x 4

    auto stage_B = [&](int c, int sn) {
        int k0 = c * BK;
        uint32_t sw = sb + SM_B0 + sn * 16384;
        #pragma unroll
        for (int i = 0; i < 2; i++) {
            int id = tid + i * 512;
            int r = id >> 2, ch = id & 3;
            cp_async16(sw + r * 64 + ((ch ^ ((r >> 1) & 3)) << 4),
                       g_w + (size_t)r * KDIM + k0 + ch * 8);
        }
    };
    auto gather = [&](int c) {
        int cin = (c & 7) * 32;                       // ci block
        const float* xp = xTb + cin + l;
        #pragma unroll
        for (int px = 0; px < 8; px++) {
            int4 f = idx_sm[px];
            cv[px][0] = xp[f.x];
            cv[px][1] = xp[f.y];
            cv[px][2] = xp[f.z];
            cv[px][3] = xp[f.w];
        }
    };
    auto convert_sts = [&](int sn) {
        uint32_t sa = sb + SM_A0 + sn * 8192;
        #pragma unroll
        for (int px = 0; px < 8; px++) {
            float4 w4 = wts_sm[px];
            float v = w4.x * cv[px][0] + w4.y * cv[px][1]
                    + w4.z * cv[px][2] + w4.w * cv[px][3];
            float vo = __shfl_down_sync(0xFFFFFFFFu, v, 1);
            if (!(l & 1)) {
                __half2 h2 = __floats2half2_rn(v, vo);
                int p = wid * 8 + px;
                int ch = l >> 3;
                sts32(sa + p * 64 + ((ch ^ ((p >> 1) & 3)) << 4) + ((l * 2) & 15),
                      *(uint32_t*)&h2);
            }
        }
    };
    auto mma_chunk = [&](int s) {
        uint32_t sa = sb + SM_A0 + s * 8192;
        uint32_t sw = sb + SM_B0 + s * 16384;
        #pragma unroll
        for (int st = 0; st < 2; st++) {             // two k16 steps
            uint32_t af[4][4];
            #pragma unroll
            for (int mi = 0; mi < 4; mi++) {
                int r = wm * 64 + mi * 16 + laneA_r;
                int ch = 2 * st + laneA_c;
                ldsm4(af[mi][0], af[mi][1], af[mi][2], af[mi][3],
                      sa + r * 64 + ((ch ^ ((r >> 1) & 3)) << 4));
            }
            uint32_t bf[4][2];
            #pragma unroll
            for (int nj = 0; nj < 2; nj++) {
                int r = wn * 32 + nj * 16 + laneB_r;
                int ch = 2 * st + laneB_c;
                uint32_t r0, r1, r2, r3;
                ldsm4(r0, r1, r2, r3,
                      sw + r * 64 + ((ch ^ ((r >> 1) & 3)) << 4));
                bf[nj * 2][0] = r0;      bf[nj * 2][1] = r1;
                bf[nj * 2 + 1][0] = r2;  bf[nj * 2 + 1][1] = r3;
            }
            #pragma unroll
            for (int mi = 0; mi < 4; mi++)
                #pragma unroll
                for (int ni = 0; ni < 4; ni++)
                    mma16816(acc[mi][ni], af[mi], bf[ni]);
        }
    };

    // ---- prologue: chunk 0 ----
    calc_off(0);
    stage_B(0, 0); CP_COMMIT();
    gather(0);
    convert_sts(0);
    CP_WAIT0();
    __syncthreads();

    // ---- mainloop ----
    for (int c = 0; c < NCH; c++) {
        int s = c & 1, sn = s ^ 1;
        int cn = c + 1;
        if (cn < NCH) {
            if ((cn & 7) == 0) calc_off(cn >> 3);
            stage_B(cn, sn); CP_COMMIT();
            gather(cn);
        }
        mma_chunk(s);
        if (cn < NCH) {
            convert_sts(sn);
            CP_WAIT0();
        }
        __syncthreads();
    }

    // ---- epilogue: acc[m][n] -> out[b][n][pt*128 + m] ----
    float* ob = out + (size_t)b * CO_ * HW_ + (size_t)pt * 128;
    int mrow = wm * 64 + (l >> 2);
    int ncol = wn * 32 + ((l & 3) << 1);
    #pragma unroll
    for (int mi = 0; mi < 4; mi++) {
        #pragma unroll
        for (int ni = 0; ni < 4; ni++) {
            int m = mrow + mi * 16;
            int n = ncol + ni * 8;
            ob[(size_t)n * HW_ + m]           = acc[mi][ni][0];
            ob[(size_t)(n + 1) * HW_ + m]     = acc[mi][ni][1];
            ob[(size_t)n * HW_ + m + 8]       = acc[mi][ni][2];
            ob[(size_t)(n + 1) * HW_ + m + 8] = acc[mi][ni][3];
        }
    }
}

// ---------------------------------------------------------------------------
extern "C" void kernel_launch(void* const* d_in, const int* in_sizes, int n_in,
                              void* d_out, int out_size)
{
    const float* x   = (const float*)d_in[0];   // [4,256,64,64]
    const float* off = (const float*)d_in[1];   // [4,18,64,64]
    const float* wt  = (const float*)d_in[2];   // [256,256,3,3]
    float* out = (float*)d_out;                 // [4,256,64,64]

    cudaFuncSetAttribute(fused_kernel,
                         cudaFuncAttributeMaxDynamicSharedMemorySize, SM_TOTAL);

    dim3 tgrid(HW_ / 32, CI_ / 32, B_);
    transpose_kernel<<<tgrid, dim3(32, 8)>>>(x);
    repack_w_kernel<<<CO_ * KK_, 256>>>(wt);

    dim3 grid(HW_ / 128, B_);                   // 32 x 4 = 128 CTAs
    fused_kernel<<<grid, 512, SM_TOTAL>>>(off, out);
}

// round 6
// speedup vs baseline: 7.0739x; 1.4544x over previous
#include <cuda_runtime.h>
#include <cuda_fp16.h>
#include <cstdint>
#include <cstddef>

// Problem constants
#define B_    4
#define CI_   256
#define CO_   256
#define H_    64
#define W_    64
#define HW_   4096
#define KK_   9
#define KDIM  2304          // CI_*KK_

// channel-last fp16 input, stored as u32 (half2 pairs): xT[(b*4096+hw)*256 + ci]
__device__ uint32_t g_xT[(size_t)B_ * HW_ * CI_ / 2];   // 33.5 MB
// fp16 repacked weight: w[co][k'] with k' = kk*256 + ci
__device__ __half g_w[(size_t)CO_ * KDIM];              // 1.2 MB

// ---------------------------------------------------------------------------
// Helpers
// ---------------------------------------------------------------------------
__device__ __forceinline__ uint32_t smem_u32(const void* p) {
    uint32_t a;
    asm("{ .reg .u64 t; cvta.to.shared.u64 t, %1; cvt.u32.u64 %0, t; }" : "=r"(a) : "l"(p));
    return a;
}
__device__ __forceinline__ void cp_async16(uint32_t dst, const void* src) {
    asm volatile("cp.async.cg.shared.global [%0], [%1], 16;" :: "r"(dst), "l"(src));
}
#define CP_COMMIT() asm volatile("cp.async.commit_group;" ::: "memory")
#define CP_WAIT0()  asm volatile("cp.async.wait_group 0;" ::: "memory")

__device__ __forceinline__ void ldsm4(uint32_t& r0, uint32_t& r1, uint32_t& r2,
                                      uint32_t& r3, uint32_t addr) {
    asm volatile("ldmatrix.sync.aligned.m8n8.x4.shared.b16 {%0,%1,%2,%3}, [%4];"
                 : "=r"(r0), "=r"(r1), "=r"(r2), "=r"(r3) : "r"(addr));
}
__device__ __forceinline__ void mma16816(float* c, const uint32_t* a, const uint32_t* b) {
    asm volatile(
        "mma.sync.aligned.m16n8k16.row.col.f32.f16.f16.f32 "
        "{%0,%1,%2,%3}, {%4,%5,%6,%7}, {%8,%9}, {%0,%1,%2,%3};"
        : "+f"(c[0]), "+f"(c[1]), "+f"(c[2]), "+f"(c[3])
        : "r"(a[0]), "r"(a[1]), "r"(a[2]), "r"(a[3]), "r"(b[0]), "r"(b[1]));
}
__device__ __forceinline__ void sts32(uint32_t addr, uint32_t v) {
    asm volatile("st.shared.b32 [%0], %1;" :: "r"(addr), "r"(v) : "memory");
}

// ---------------------------------------------------------------------------
// Kernel 1: tiled transpose+convert  x[b][ci][hw] (f32) -> g_xT[b][hw][ci] (f16)
// ---------------------------------------------------------------------------
__global__ __launch_bounds__(256) void transpose_kernel(const float* __restrict__ x) {
    __shared__ float sm[32][33];
    int hw0 = blockIdx.x * 32;
    int ci0 = blockIdx.y * 32;
    int b   = blockIdx.z;
    int tid = threadIdx.x;                 // 256 threads
    int tx = tid & 31, ty = tid >> 5;      // (32, 8)

    const float* xb = x + (size_t)b * CI_ * HW_;
    #pragma unroll
    for (int i = 0; i < 4; i++)
        sm[ty + i * 8][tx] = xb[(size_t)(ci0 + ty + i * 8) * HW_ + hw0 + tx];
    __syncthreads();

    uint32_t* xtb = g_xT + (size_t)b * HW_ * CI_ / 2;
    #pragma unroll
    for (int rep = 0; rep < 2; rep++) {
        int t = tid + rep * 256;
        int hwl = t >> 4;                  // 0..31
        int cip = t & 15;                  // ci pair index
        __half2 h2 = __floats2half2_rn(sm[2 * cip][hwl], sm[2 * cip + 1][hwl]);
        xtb[(size_t)(hw0 + hwl) * (CI_ / 2) + ci0 / 2 + cip] = *(uint32_t*)&h2;
    }
}

// ---------------------------------------------------------------------------
// Kernel 2: weight repack  g_w[co][kk*256+ci] = (half) W[co][ci][kk]
// ---------------------------------------------------------------------------
__global__ __launch_bounds__(256) void repack_w_kernel(const float* __restrict__ w) {
    int ck = blockIdx.x;            // co*9 + kk
    int ci = threadIdx.x;
    int co = ck / KK_, kk = ck % KK_;
    g_w[(size_t)ck * CI_ + ci] = __float2half(w[((size_t)co * CI_ + ci) * KK_ + kk]);
}

// ---------------------------------------------------------------------------
// Kernel 3: fused deformable im2col + HMMA GEMM
// CTA: 128 px x 256 co, 512 threads (16 warps, 2x8), K in 36 chunks of 64.
// A gathered in-kernel from fp16 xT (half2 loads, shfl-free convert);
// B double-buffered via cp.async. SW128 swizzle on 128B rows: ch ^= (row&7).
// ---------------------------------------------------------------------------
#define BK 64
#define NCH (KDIM / BK)       // 36
#define SM_A0   0             // 2 x 16384 (A: 128 x 64 half)
#define SM_B0   32768         // 2 x 32768 (B: 256 x 64 half)
#define SM_IDX  98304         // int4  [16][8]
#define SM_WTS  100352        // float4[16][8]
#define SM_TOTAL 102400

__global__ __launch_bounds__(512, 1) void fused_kernel(
    const float* __restrict__ offset, float* __restrict__ out)
{
    extern __shared__ char smem[];
    uint32_t sb = smem_u32(smem);
    int tid = threadIdx.x, wid = tid >> 5, l = tid & 31;
    int pt = blockIdx.x;      // pixel tile 0..31
    int b  = blockIdx.y;

    int4*   idx_sm = (int4*)(smem + SM_IDX)  + wid * 8;
    float4* wts_sm = (float4*)(smem + SM_WTS) + wid * 8;

    const float*  offb = offset + (size_t)b * 18 * HW_;
    const __half* xTb  = (const __half*)g_xT + (size_t)b * HW_ * CI_;

    // bilinear corner offsets/weights for this warp's 8 pixels at tap kk
    auto calc_off = [&](int kk) {
        if (l < 8) {
            int pg = pt * 128 + wid * 8 + l;
            int h = pg >> 6, w = pg & 63;
            float offy = offb[(size_t)(2 * kk)     * HW_ + pg];
            float offx = offb[(size_t)(2 * kk + 1) * HW_ + pg];
            int i = kk / 3, j = kk % 3;
            float py = (float)(h + i) + offy;   // padded coords
            float px = (float)(w + j) + offx;
            float y0f = floorf(py), x0f = floorf(px);
            float ly = py - y0f, lx = px - x0f;
            int y0 = (int)y0f - 1, x0 = (int)x0f - 1;   // unpadded
            float wt[4] = { (1.f - ly) * (1.f - lx), (1.f - ly) * lx,
                            ly * (1.f - lx),          ly * lx };
            int fl[4];
            #pragma unroll
            for (int c = 0; c < 4; c++) {
                int yi = y0 + (c >> 1), xi = x0 + (c & 1);
                bool v = (yi >= 0) & (yi < H_) & (xi >= 0) & (xi < W_);
                fl[c] = v ? (yi * W_ + xi) * CI_ : 0;   // half-element offset
                if (!v) wt[c] = 0.f;
            }
            idx_sm[l] = make_int4(fl[0], fl[1], fl[2], fl[3]);
            wts_sm[l] = make_float4(wt[0], wt[1], wt[2], wt[3]);
        }
        __syncwarp();
    };

    float acc[4][4][4];
    #pragma unroll
    for (int a = 0; a < 4; a++)
        #pragma unroll
        for (int bb = 0; bb < 4; bb++)
            #pragma unroll
            for (int cc = 0; cc < 4; cc++) acc[a][bb][cc] = 0.f;

    // MMA warp layout (2 x 8): warp tile 64 px x 32 co
    int wm = wid >> 3;        // 0..1
    int wn = wid & 7;         // 0..7
    int laneA_r = l & 15;
    int laneA_c = l >> 4;
    int laneB_r = (l & 7) + ((l >> 4) << 3);
    int laneB_c = (l >> 3) & 1;

    uint32_t cv[4][4];        // 4 px in flight x 4 corners (half2 each)

    auto stage_B = [&](int c, int sn) {
        int k0 = c * BK;
        uint32_t sw = sb + SM_B0 + sn * 32768;
        #pragma unroll
        for (int i = 0; i < 4; i++) {           // 2048 16B chunks / 512 thr
            int id = tid + i * 512;
            int r = id >> 3, ch = id & 7;
            cp_async16(sw + r * 128 + ((ch ^ (r & 7)) << 4),
                       g_w + (size_t)r * KDIM + k0 + ch * 8);
        }
    };
    auto gather4 = [&](int c, int base) {
        int cin = (c & 3) * 64;                 // ci block within tap
        const __half* xp = xTb + cin + 2 * l;   // this lane's ci pair
        #pragma unroll
        for (int px = 0; px < 4; px++) {
            int4 f = idx_sm[base + px];
            cv[px][0] = *(const uint32_t*)(xp + f.x);
            cv[px][1] = *(const uint32_t*)(xp + f.y);
            cv[px][2] = *(const uint32_t*)(xp + f.z);
            cv[px][3] = *(const uint32_t*)(xp + f.w);
        }
    };
    auto convert4 = [&](int sn, int base) {
        uint32_t sa = sb + SM_A0 + sn * 16384;
        #pragma unroll
        for (int px = 0; px < 4; px++) {
            float4 w4 = wts_sm[base + px];
            float2 a0 = __half22float2(*(__half2*)&cv[px][0]);
            float2 a1 = __half22float2(*(__half2*)&cv[px][1]);
            float2 a2 = __half22float2(*(__half2*)&cv[px][2]);
            float2 a3 = __half22float2(*(__half2*)&cv[px][3]);
            float v0 = w4.x * a0.x + w4.y * a1.x + w4.z * a2.x + w4.w * a3.x;
            float v1 = w4.x * a0.y + w4.y * a1.y + w4.z * a2.y + w4.w * a3.y;
            __half2 h2 = __floats2half2_rn(v0, v1);
            int p = wid * 8 + base + px;
            sts32(sa + p * 128 + ((((l >> 2)) ^ (p & 7)) << 4) + ((l & 3) << 2),
                  *(uint32_t*)&h2);
        }
    };
    auto mma_steps = [&](int s, int st0) {
        uint32_t sa = sb + SM_A0 + s * 16384;
        uint32_t sw = sb + SM_B0 + s * 32768;
        #pragma unroll
        for (int st = st0; st < st0 + 2; st++) {     // k16 steps
            uint32_t af[4][4];
            #pragma unroll
            for (int mi = 0; mi < 4; mi++) {
                int r = wm * 64 + mi * 16 + laneA_r;
                int ch = 2 * st + laneA_c;
                ldsm4(af[mi][0], af[mi][1], af[mi][2], af[mi][3],
                      sa + r * 128 + ((ch ^ (r & 7)) << 4));
            }
            uint32_t bf[4][2];
            #pragma unroll
            for (int nj = 0; nj < 2; nj++) {
                int r = wn * 32 + nj * 16 + laneB_r;
                int ch = 2 * st + laneB_c;
                uint32_t r0, r1, r2, r3;
                ldsm4(r0, r1, r2, r3,
                      sw + r * 128 + ((ch ^ (r & 7)) << 4));
                bf[nj * 2][0] = r0;      bf[nj * 2][1] = r1;
                bf[nj * 2 + 1][0] = r2;  bf[nj * 2 + 1][1] = r3;
            }
            #pragma unroll
            for (int mi = 0; mi < 4; mi++)
                #pragma unroll
                for (int ni = 0; ni < 4; ni++)
                    mma16816(acc[mi][ni], af[mi], bf[ni]);
        }
    };

    // ---- prologue: chunk 0 ----
    calc_off(0);
    stage_B(0, 0); CP_COMMIT();
    gather4(0, 0); convert4(0, 0);
    gather4(0, 4); convert4(0, 4);
    CP_WAIT0();
    __syncthreads();

    // ---- mainloop ----
    for (int c = 0; c < NCH; c++) {
        int s = c & 1, sn = s ^ 1;
        int cn = c + 1;
        bool more = (cn < NCH);
        if (more) {
            if ((cn & 3) == 0) calc_off(cn >> 2);
            stage_B(cn, sn);
        }
        CP_COMMIT();
        if (more) gather4(cn, 0);
        mma_steps(s, 0);
        if (more) { convert4(sn, 0); gather4(cn, 4); }
        mma_steps(s, 2);
        if (more) convert4(sn, 4);
        CP_WAIT0();
        __syncthreads();
    }

    // ---- epilogue: acc[m][n] -> out[b][n][pt*128 + m] ----
    float* ob = out + (size_t)b * CO_ * HW_ + (size_t)pt * 128;
    int mrow = wm * 64 + (l >> 2);
    int ncol = wn * 32 + ((l & 3) << 1);
    #pragma unroll
    for (int mi = 0; mi < 4; mi++) {
        #pragma unroll
        for (int ni = 0; ni < 4; ni++) {
            int m = mrow + mi * 16;
            int n = ncol + ni * 8;
            ob[(size_t)n * HW_ + m]           = acc[mi][ni][0];
            ob[(size_t)(n + 1) * HW_ + m]     = acc[mi][ni][1];
            ob[(size_t)n * HW_ + m + 8]       = acc[mi][ni][2];
            ob[(size_t)(n + 1) * HW_ + m + 8] = acc[mi][ni][3];
        }
    }
}

// ---------------------------------------------------------------------------
extern "C" void kernel_launch(void* const* d_in, const int* in_sizes, int n_in,
                              void* d_out, int out_size)
{
    const float* x   = (const float*)d_in[0];   // [4,256,64,64]
    const float* off = (const float*)d_in[1];   // [4,18,64,64]
    const float* wt  = (const float*)d_in[2];   // [256,256,3,3]
    float* out = (float*)d_out;                 // [4,256,64,64]

    cudaFuncSetAttribute(fused_kernel,
                         cudaFuncAttributeMaxDynamicSharedMemorySize, SM_TOTAL);

    dim3 tgrid(HW_ / 32, CI_ / 32, B_);
    transpose_kernel<<<tgrid, 256>>>(x);
    repack_w_kernel<<<CO_ * KK_, 256>>>(wt);

    dim3 grid(HW_ / 128, B_);                   // 32 x 4 = 128 CTAs
    fused_kernel<<<grid, 512, SM_TOTAL>>>(off, out);
}

// round 7
// speedup vs baseline: 7.0929x; 1.0027x over previous
#include <cuda_runtime.h>
#include <cuda_fp16.h>
#include <cstdint>
#include <cstddef>

// Problem constants
#define B_    4
#define CI_   256
#define CO_   256
#define H_    64
#define W_    64
#define HW_   4096
#define KK_   9
#define KDIM  2304          // CI_*KK_

// channel-last fp16 input, stored as u32 (half2 pairs): xT[(b*4096+hw)*256 + ci]
__device__ uint32_t g_xT[(size_t)B_ * HW_ * CI_ / 2];   // 8.4 MB
// fp16 repacked weight: w[co][k'] with k' = kk*256 + ci
__device__ __half g_w[(size_t)CO_ * KDIM];              // 1.2 MB

// ---------------------------------------------------------------------------
// Helpers
// ---------------------------------------------------------------------------
__device__ __forceinline__ uint32_t smem_u32(const void* p) {
    uint32_t a;
    asm("{ .reg .u64 t; cvta.to.shared.u64 t, %1; cvt.u32.u64 %0, t; }" : "=r"(a) : "l"(p));
    return a;
}
__device__ __forceinline__ void cp_async16(uint32_t dst, const void* src) {
    asm volatile("cp.async.cg.shared.global [%0], [%1], 16;" :: "r"(dst), "l"(src));
}
#define CP_COMMIT() asm volatile("cp.async.commit_group;" ::: "memory")
#define CP_WAIT0()  asm volatile("cp.async.wait_group 0;" ::: "memory")

__device__ __forceinline__ void ldsm4(uint32_t& r0, uint32_t& r1, uint32_t& r2,
                                      uint32_t& r3, uint32_t addr) {
    asm volatile("ldmatrix.sync.aligned.m8n8.x4.shared.b16 {%0,%1,%2,%3}, [%4];"
                 : "=r"(r0), "=r"(r1), "=r"(r2), "=r"(r3) : "r"(addr));
}
__device__ __forceinline__ void mma16816(float* c, const uint32_t* a, const uint32_t* b) {
    asm volatile(
        "mma.sync.aligned.m16n8k16.row.col.f32.f16.f16.f32 "
        "{%0,%1,%2,%3}, {%4,%5,%6,%7}, {%8,%9}, {%0,%1,%2,%3};"
        : "+f"(c[0]), "+f"(c[1]), "+f"(c[2]), "+f"(c[3])
        : "r"(a[0]), "r"(a[1]), "r"(a[2]), "r"(a[3]), "r"(b[0]), "r"(b[1]));
}
__device__ __forceinline__ void sts32(uint32_t addr, uint32_t v) {
    asm volatile("st.shared.b32 [%0], %1;" :: "r"(addr), "r"(v) : "memory");
}

// ---------------------------------------------------------------------------
// Kernel 1: merged prep.
//   z < 4 : tiled transpose+convert  x[b][ci][hw] (f32) -> xT[b][hw][ci] (f16)
//   z == 4: grid-stride weight repack g_w[co][kk*256+ci] = (half) W[co][ci][kk]
// ---------------------------------------------------------------------------
__global__ __launch_bounds__(256) void prep_kernel(
    const float* __restrict__ x, const float* __restrict__ w)
{
    int z = blockIdx.z;
    int tid = threadIdx.x;

    if (z < B_) {
        __shared__ float sm[32][33];
        int hw0 = blockIdx.x * 32;
        int ci0 = blockIdx.y * 32;
        int b   = z;
        int tx = tid & 31, ty = tid >> 5;      // (32, 8)

        const float* xb = x + (size_t)b * CI_ * HW_;
        #pragma unroll
        for (int i = 0; i < 4; i++)
            sm[ty + i * 8][tx] = xb[(size_t)(ci0 + ty + i * 8) * HW_ + hw0 + tx];
        __syncthreads();

        uint32_t* xtb = g_xT + (size_t)b * HW_ * CI_ / 2;
        #pragma unroll
        for (int rep = 0; rep < 2; rep++) {
            int t = tid + rep * 256;
            int hwl = t >> 4;                  // 0..31
            int cip = t & 15;                  // ci pair index
            __half2 h2 = __floats2half2_rn(sm[2 * cip][hwl], sm[2 * cip + 1][hwl]);
            xtb[(size_t)(hw0 + hwl) * (CI_ / 2) + ci0 / 2 + cip] = *(uint32_t*)&h2;
        }
    } else {
        int rb = blockIdx.x * gridDim.y + blockIdx.y;     // 0..1023
        for (int ck = rb; ck < CO_ * KK_; ck += 1024) {   // co*9 + kk
            int co = ck / KK_, kk = ck % KK_;
            g_w[(size_t)ck * CI_ + tid] =
                __float2half(w[((size_t)co * CI_ + tid) * KK_ + kk]);
        }
    }
}

// ---------------------------------------------------------------------------
// Kernel 2: fused deformable im2col + HMMA GEMM
// CTA: 64 px x 256 co, 256 threads (8 warps, warp tile 64x32), K = 36 x 64.
// 2 CTAs/SM for cross-CTA latency hiding. A gathered in-kernel from fp16 xT;
// B double-buffered via cp.async. SW128 swizzle on 128B rows: ch ^= (row&7).
// ---------------------------------------------------------------------------
#define BM 64
#define BK 64
#define NCH (KDIM / BK)       // 36
#define SM_A0   0             // 2 x 8192  (A: 64 x 64 half)
#define SM_B0   16384         // 2 x 32768 (B: 256 x 64 half)
#define SM_IDX  81920         // int4  [8][8]   (1 KB)
#define SM_WTS  82944         // float4[8][8]   (1 KB)
#define SM_TOTAL 83968

__global__ __launch_bounds__(256, 2) void fused_kernel(
    const float* __restrict__ offset, float* __restrict__ out)
{
    extern __shared__ char smem[];
    uint32_t sb = smem_u32(smem);
    int tid = threadIdx.x, wid = tid >> 5, l = tid & 31;
    int pt = blockIdx.x;      // pixel tile 0..63
    int b  = blockIdx.y;

    int4*   idx_sm = (int4*)(smem + SM_IDX)  + wid * 8;
    float4* wts_sm = (float4*)(smem + SM_WTS) + wid * 8;

    const float*  offb = offset + (size_t)b * 18 * HW_;
    const __half* xTb  = (const __half*)g_xT + (size_t)b * HW_ * CI_;

    // bilinear corner offsets/weights for this warp's 8 pixels at tap kk
    auto calc_off = [&](int kk) {
        if (l < 8) {
            int pg = pt * BM + wid * 8 + l;
            int h = pg >> 6, w = pg & 63;
            float offy = offb[(size_t)(2 * kk)     * HW_ + pg];
            float offx = offb[(size_t)(2 * kk + 1) * HW_ + pg];
            int i = kk / 3, j = kk % 3;
            float py = (float)(h + i) + offy;   // padded coords
            float px = (float)(w + j) + offx;
            float y0f = floorf(py), x0f = floorf(px);
            float ly = py - y0f, lx = px - x0f;
            int y0 = (int)y0f - 1, x0 = (int)x0f - 1;   // unpadded
            float wt[4] = { (1.f - ly) * (1.f - lx), (1.f - ly) * lx,
                            ly * (1.f - lx),          ly * lx };
            int fl[4];
            #pragma unroll
            for (int c = 0; c < 4; c++) {
                int yi = y0 + (c >> 1), xi = x0 + (c & 1);
                bool v = (yi >= 0) & (yi < H_) & (xi >= 0) & (xi < W_);
                fl[c] = v ? (yi * W_ + xi) * CI_ : 0;   // half-element offset
                if (!v) wt[c] = 0.f;
            }
            idx_sm[l] = make_int4(fl[0], fl[1], fl[2], fl[3]);
            wts_sm[l] = make_float4(wt[0], wt[1], wt[2], wt[3]);
        }
        __syncwarp();
    };

    float acc[4][4][4];
    #pragma unroll
    for (int a = 0; a < 4; a++)
        #pragma unroll
        for (int bb = 0; bb < 4; bb++)
            #pragma unroll
            for (int cc = 0; cc < 4; cc++) acc[a][bb][cc] = 0.f;

    // warp tile: 64 px x 32 co;  wn = wid selects co slab
    int wn = wid;
    int laneA_r = l & 15;
    int laneA_c = l >> 4;
    int laneB_r = (l & 7) + ((l >> 4) << 3);
    int laneB_c = (l >> 3) & 1;

    uint32_t cv[4][4];        // 4 px in flight x 4 corners (half2 each)

    auto stage_B = [&](int c, int sn) {
        int k0 = c * BK;
        uint32_t sw = sb + SM_B0 + sn * 32768;
        #pragma unroll
        for (int i = 0; i < 8; i++) {           // 2048 16B chunks / 256 thr
            int id = tid + i * 256;
            int r = id >> 3, ch = id & 7;
            cp_async16(sw + r * 128 + ((ch ^ (r & 7)) << 4),
                       g_w + (size_t)r * KDIM + k0 + ch * 8);
        }
    };
    auto gather4 = [&](int c, int base) {
        int cin = (c & 3) * 64;                 // ci block within tap
        const __half* xp = xTb + cin + 2 * l;   // this lane's ci pair
        #pragma unroll
        for (int px = 0; px < 4; px++) {
            int4 f = idx_sm[base + px];
            cv[px][0] = *(const uint32_t*)(xp + f.x);
            cv[px][1] = *(const uint32_t*)(xp + f.y);
            cv[px][2] = *(const uint32_t*)(xp + f.z);
            cv[px][3] = *(const uint32_t*)(xp + f.w);
        }
    };
    auto convert4 = [&](int sn, int base) {
        uint32_t sa = sb + SM_A0 + sn * 8192;
        #pragma unroll
        for (int px = 0; px < 4; px++) {
            float4 w4 = wts_sm[base + px];
            float2 a0 = __half22float2(*(__half2*)&cv[px][0]);
            float2 a1 = __half22float2(*(__half2*)&cv[px][1]);
            float2 a2 = __half22float2(*(__half2*)&cv[px][2]);
            float2 a3 = __half22float2(*(__half2*)&cv[px][3]);
            float v0 = w4.x * a0.x + w4.y * a1.x + w4.z * a2.x + w4.w * a3.x;
            float v1 = w4.x * a0.y + w4.y * a1.y + w4.z * a2.y + w4.w * a3.y;
            __half2 h2 = __floats2half2_rn(v0, v1);
            int p = wid * 8 + base + px;        // A row 0..63
            sts32(sa + p * 128 + (((l >> 2) ^ (p & 7)) << 4) + ((l & 3) << 2),
                  *(uint32_t*)&h2);
        }
    };
    auto mma_steps = [&](int s, int st0) {
        uint32_t sa = sb + SM_A0 + s * 8192;
        uint32_t sw = sb + SM_B0 + s * 32768;
        #pragma unroll
        for (int st = st0; st < st0 + 2; st++) {     // k16 steps
            uint32_t af[4][4];
            #pragma unroll
            for (int mi = 0; mi < 4; mi++) {
                int r = mi * 16 + laneA_r;
                int ch = 2 * st + laneA_c;
                ldsm4(af[mi][0], af[mi][1], af[mi][2], af[mi][3],
                      sa + r * 128 + ((ch ^ (r & 7)) << 4));
            }
            uint32_t bf[4][2];
            #pragma unroll
            for (int nj = 0; nj < 2; nj++) {
                int r = wn * 32 + nj * 16 + laneB_r;
                int ch = 2 * st + laneB_c;
                uint32_t r0, r1, r2, r3;
                ldsm4(r0, r1, r2, r3,
                      sw + r * 128 + ((ch ^ (r & 7)) << 4));
                bf[nj * 2][0] = r0;      bf[nj * 2][1] = r1;
                bf[nj * 2 + 1][0] = r2;  bf[nj * 2 + 1][1] = r3;
            }
            #pragma unroll
            for (int mi = 0; mi < 4; mi++)
                #pragma unroll
                for (int ni = 0; ni < 4; ni++)
                    mma16816(acc[mi][ni], af[mi], bf[ni]);
        }
    };

    // ---- prologue: chunk 0 ----
    calc_off(0);
    stage_B(0, 0); CP_COMMIT();
    gather4(0, 0); convert4(0, 0);
    gather4(0, 4); convert4(0, 4);
    CP_WAIT0();
    __syncthreads();

    // ---- mainloop ----
    for (int c = 0; c < NCH; c++) {
        int s = c & 1, sn = s ^ 1;
        int cn = c + 1;
        bool more = (cn < NCH);
        if (more) {
            if ((cn & 3) == 0) calc_off(cn >> 2);
            stage_B(cn, sn);
        }
        CP_COMMIT();
        if (more) gather4(cn, 0);
        mma_steps(s, 0);
        if (more) { convert4(sn, 0); gather4(cn, 4); }
        mma_steps(s, 2);
        if (more) convert4(sn, 4);
        CP_WAIT0();
        __syncthreads();
    }

    // ---- epilogue: acc[m][n] -> out[b][n][pt*64 + m] ----
    float* ob = out + (size_t)b * CO_ * HW_ + (size_t)pt * BM;
    int mrow = l >> 2;
    int ncol = wn * 32 + ((l & 3) << 1);
    #pragma unroll
    for (int mi = 0; mi < 4; mi++) {
        #pragma unroll
        for (int ni = 0; ni < 4; ni++) {
            int m = mrow + mi * 16;
            int n = ncol + ni * 8;
            ob[(size_t)n * HW_ + m]           = acc[mi][ni][0];
            ob[(size_t)(n + 1) * HW_ + m]     = acc[mi][ni][1];
            ob[(size_t)n * HW_ + m + 8]       = acc[mi][ni][2];
            ob[(size_t)(n + 1) * HW_ + m + 8] = acc[mi][ni][3];
        }
    }
}

// ---------------------------------------------------------------------------
extern "C" void kernel_launch(void* const* d_in, const int* in_sizes, int n_in,
                              void* d_out, int out_size)
{
    const float* x   = (const float*)d_in[0];   // [4,256,64,64]
    const float* off = (const float*)d_in[1];   // [4,18,64,64]
    const float* wt  = (const float*)d_in[2];   // [256,256,3,3]
    float* out = (float*)d_out;                 // [4,256,64,64]

    cudaFuncSetAttribute(fused_kernel,
                         cudaFuncAttributeMaxDynamicSharedMemorySize, SM_TOTAL);

    dim3 pgrid(HW_ / 32, CI_ / 32, B_ + 1);     // transpose planes + repack plane
    prep_kernel<<<pgrid, 256>>>(x, wt);

    dim3 grid(HW_ / BM, B_);                    // 64 x 4 = 256 CTAs
    fused_kernel<<<grid, 256, SM_TOTAL>>>(off, out);
}

// round 9
// speedup vs baseline: 7.4208x; 1.0462x over previous
#include <cuda_runtime.h>
#include <cuda_fp16.h>
#include <cstdint>
#include <cstddef>

// Problem constants
#define B_    4
#define CI_   256
#define CO_   256
#define H_    64
#define W_    64
#define HW_   4096
#define KK_   9
#define KDIM  2304          // CI_*KK_

// channel-last fp16 input, stored as u32 (half2 pairs): xT[(b*4096+hw)*256 + ci]
__device__ uint32_t g_xT[(size_t)B_ * HW_ * CI_ / 2];   // 8.4 MB
// fp16 repacked weight: w[co][k'] with k' = kk*256 + ci
__device__ __half g_w[(size_t)CO_ * KDIM];              // 1.2 MB

// ---------------------------------------------------------------------------
// Helpers
// ---------------------------------------------------------------------------
__device__ __forceinline__ uint32_t smem_u32(const void* p) {
    uint32_t a;
    asm("{ .reg .u64 t; cvta.to.shared.u64 t, %1; cvt.u32.u64 %0, t; }" : "=r"(a) : "l"(p));
    return a;
}
__device__ __forceinline__ void cp_async16(uint32_t dst, const void* src) {
    asm volatile("cp.async.cg.shared.global [%0], [%1], 16;" :: "r"(dst), "l"(src));
}
#define CP_COMMIT() asm volatile("cp.async.commit_group;" ::: "memory")
#define CP_WAIT0()  asm volatile("cp.async.wait_group 0;" ::: "memory")

__device__ __forceinline__ void ldsm4(uint32_t& r0, uint32_t& r1, uint32_t& r2,
                                      uint32_t& r3, uint32_t addr) {
    asm volatile("ldmatrix.sync.aligned.m8n8.x4.shared.b16 {%0,%1,%2,%3}, [%4];"
                 : "=r"(r0), "=r"(r1), "=r"(r2), "=r"(r3) : "r"(addr));
}
__device__ __forceinline__ void mma16816(float* c, const uint32_t* a, const uint32_t* b) {
    asm volatile(
        "mma.sync.aligned.m16n8k16.row.col.f32.f16.f16.f32 "
        "{%0,%1,%2,%3}, {%4,%5,%6,%7}, {%8,%9}, {%0,%1,%2,%3};"
        : "+f"(c[0]), "+f"(c[1]), "+f"(c[2]), "+f"(c[3])
        : "r"(a[0]), "r"(a[1]), "r"(a[2]), "r"(a[3]), "r"(b[0]), "r"(b[1]));
}
__device__ __forceinline__ void sts32(uint32_t addr, uint32_t v) {
    asm volatile("st.shared.b32 [%0], %1;" :: "r"(addr), "r"(v) : "memory");
}

// ---------------------------------------------------------------------------
// Kernel 1: merged prep.
//   z < 4 : tiled transpose+convert  x[b][ci][hw] (f32) -> xT[b][hw][ci] (f16)
//   z == 4: grid-stride weight repack g_w[co][kk*256+ci] = (half) W[co][ci][kk]
// ---------------------------------------------------------------------------
__global__ __launch_bounds__(256) void prep_kernel(
    const float* __restrict__ x, const float* __restrict__ w)
{
    int z = blockIdx.z;
    int tid = threadIdx.x;

    if (z < B_) {
        __shared__ float sm[32][33];
        int hw0 = blockIdx.x * 32;
        int ci0 = blockIdx.y * 32;
        int b   = z;
        int tx = tid & 31, ty = tid >> 5;      // (32, 8)

        const float* xb = x + (size_t)b * CI_ * HW_;
        #pragma unroll
        for (int i = 0; i < 4; i++)
            sm[ty + i * 8][tx] = xb[(size_t)(ci0 + ty + i * 8) * HW_ + hw0 + tx];
        __syncthreads();

        uint32_t* xtb = g_xT + (size_t)b * HW_ * CI_ / 2;
        #pragma unroll
        for (int rep = 0; rep < 2; rep++) {
            int t = tid + rep * 256;
            int hwl = t >> 4;                  // 0..31
            int cip = t & 15;                  // ci pair index
            __half2 h2 = __floats2half2_rn(sm[2 * cip][hwl], sm[2 * cip + 1][hwl]);
            xtb[(size_t)(hw0 + hwl) * (CI_ / 2) + ci0 / 2 + cip] = *(uint32_t*)&h2;
        }
    } else {
        int rb = blockIdx.x * gridDim.y + blockIdx.y;     // 0..1023
        for (int ck = rb; ck < CO_ * KK_; ck += 1024) {   // co*9 + kk
            int co = ck / KK_, kk = ck % KK_;
            g_w[(size_t)ck * CI_ + tid] =
                __float2half(w[((size_t)co * CI_ + tid) * KK_ + kk]);
        }
    }
}

// ---------------------------------------------------------------------------
// Kernel 2: fused deformable im2col + HMMA GEMM
// CTA: 64 px x 256 co, 256 threads (8 warps, warp tile 64x32), K = 36 x 64.
// 2 CTAs/SM. A gathered in-kernel (half2), bilinear combine in HFMA2;
// B double-buffered via cp.async. SW128 swizzle on 128B rows: ch ^= (row&7).
// Mainloop unrolled x2 so stage bases are compile-time.
// ---------------------------------------------------------------------------
#define BM 64
#define BK 64
#define NCH (KDIM / BK)       // 36
#define SM_A0   0             // 2 x 8192  (A: 64 x 64 half)
#define SM_B0   16384         // 2 x 32768 (B: 256 x 64 half)
#define SM_IDX  81920         // int4  [8][8]   (1 KB)
#define SM_WTS  82944         // uint4 [8][8]   (1 KB, half2-broadcast weights)
#define SM_TOTAL 83968

__global__ __launch_bounds__(256, 2) void fused_kernel(
    const float* __restrict__ offset, float* __restrict__ out)
{
    extern __shared__ char smem[];
    uint32_t sb = smem_u32(smem);
    int tid = threadIdx.x, wid = tid >> 5, l = tid & 31;
    int pt = blockIdx.x;      // pixel tile 0..63
    int b  = blockIdx.y;

    int4*  idx_sm  = (int4*)(smem + SM_IDX)  + wid * 8;
    uint4* wts_sm  = (uint4*)(smem + SM_WTS) + wid * 8;

    const float*  offb = offset + (size_t)b * 18 * HW_;
    const __half* xTb  = (const __half*)g_xT + (size_t)b * HW_ * CI_;

    // bilinear corner offsets/weights for this warp's 8 pixels at tap kk
    auto calc_off = [&](int kk) {
        if (l < 8) {
            int pg = pt * BM + wid * 8 + l;
            int h = pg >> 6, w = pg & 63;
            float offy = offb[(size_t)(2 * kk)     * HW_ + pg];
            float offx = offb[(size_t)(2 * kk + 1) * HW_ + pg];
            int i = kk / 3, j = kk % 3;
            float py = (float)(h + i) + offy;   // padded coords
            float px = (float)(w + j) + offx;
            float y0f = floorf(py), x0f = floorf(px);
            float ly = py - y0f, lx = px - x0f;
            int y0 = (int)y0f - 1, x0 = (int)x0f - 1;   // unpadded
            float wt[4] = { (1.f - ly) * (1.f - lx), (1.f - ly) * lx,
                            ly * (1.f - lx),          ly * lx };
            int fl[4];
            uint32_t wh[4];
            #pragma unroll
            for (int c = 0; c < 4; c++) {
                int yi = y0 + (c >> 1), xi = x0 + (c & 1);
                bool v = (yi >= 0) & (yi < H_) & (xi >= 0) & (xi < W_);
                fl[c] = v ? (yi * W_ + xi) * CI_ : 0;   // half-element offset
                if (!v) wt[c] = 0.f;
                __half2 h2 = __half2half2(__float2half(wt[c]));
                wh[c] = *(uint32_t*)&h2;
            }
            idx_sm[l] = make_int4(fl[0], fl[1], fl[2], fl[3]);
            wts_sm[l] = make_uint4(wh[0], wh[1], wh[2], wh[3]);
        }
        __syncwarp();
    };

    float acc[4][4][4];
    #pragma unroll
    for (int a = 0; a < 4; a++)
        #pragma unroll
        for (int bb = 0; bb < 4; bb++)
            #pragma unroll
            for (int cc = 0; cc < 4; cc++) acc[a][bb][cc] = 0.f;

    // warp tile: 64 px x 32 co;  wn = wid selects co slab
    int wn = wid;
    int laneA_r = l & 15;
    int laneA_c = l >> 4;
    int laneB_r = (l & 7) + ((l >> 4) << 3);
    int laneB_c = (l >> 3) & 1;

    uint32_t cv[4][4];        // 4 px in flight x 4 corners (half2 each)

    auto stage_B = [&](int c, int sn) {
        int k0 = c * BK;
        uint32_t sw = sb + SM_B0 + sn * 32768;
        #pragma unroll
        for (int i = 0; i < 8; i++) {           // 2048 16B chunks / 256 thr
            int id = tid + i * 256;
            int r = id >> 3, ch = id & 7;
            cp_async16(sw + r * 128 + ((ch ^ (r & 7)) << 4),
                       g_w + (size_t)r * KDIM + k0 + ch * 8);
        }
    };
    auto gather4 = [&](int c, int base) {
        int cin = (c & 3) * 64;                 // ci block within tap
        const __half* xp = xTb + cin + 2 * l;   // this lane's ci pair
        #pragma unroll
        for (int px = 0; px < 4; px++) {
            int4 f = idx_sm[base + px];
            cv[px][0] = *(const uint32_t*)(xp + f.x);
            cv[px][1] = *(const uint32_t*)(xp + f.y);
            cv[px][2] = *(const uint32_t*)(xp + f.z);
            cv[px][3] = *(const uint32_t*)(xp + f.w);
        }
    };
    auto convert4 = [&](int sn, int base) {
        uint32_t sa = sb + SM_A0 + sn * 8192;
        #pragma unroll
        for (int px = 0; px < 4; px++) {
            uint4 w4 = wts_sm[base + px];
            __half2 v = __hmul2(*(__half2*)&cv[px][0], *(__half2*)&w4.x);
            v = __hfma2(*(__half2*)&cv[px][1], *(__half2*)&w4.y, v);
            v = __hfma2(*(__half2*)&cv[px][2], *(__half2*)&w4.z, v);
            v = __hfma2(*(__half2*)&cv[px][3], *(__half2*)&w4.w, v);
            int p = wid * 8 + base + px;        // A row 0..63
            sts32(sa + p * 128 + (((l >> 2) ^ (p & 7)) << 4) + ((l & 3) << 2),
                  *(uint32_t*)&v);
        }
    };
    auto mma_steps = [&](int s, int st0) {
        uint32_t sa = sb + SM_A0 + s * 8192;
        uint32_t sw = sb + SM_B0 + s * 32768;
        #pragma unroll
        for (int st = st0; st < st0 + 2; st++) {     // k16 steps
            uint32_t af[4][4];
            #pragma unroll
            for (int mi = 0; mi < 4; mi++) {
                int r = mi * 16 + laneA_r;
                int ch = 2 * st + laneA_c;
                ldsm4(af[mi][0], af[mi][1], af[mi][2], af[mi][3],
                      sa + r * 128 + ((ch ^ (r & 7)) << 4));
            }
            uint32_t bf[4][2];
            #pragma unroll
            for (int nj = 0; nj < 2; nj++) {
                int r = wn * 32 + nj * 16 + laneB_r;
                int ch = 2 * st + laneB_c;
                uint32_t r0, r1, r2, r3;
                ldsm4(r0, r1, r2, r3,
                      sw + r * 128 + ((ch ^ (r & 7)) << 4));
                bf[nj * 2][0] = r0;      bf[nj * 2][1] = r1;
                bf[nj * 2 + 1][0] = r2;  bf[nj * 2 + 1][1] = r3;
            }
            #pragma unroll
            for (int mi = 0; mi < 4; mi++)
                #pragma unroll
                for (int ni = 0; ni < 4; ni++)
                    mma16816(acc[mi][ni], af[mi], bf[ni]);
        }
    };

    // one chunk of the software pipeline; s must be a literal for const-fold
    auto chunk_body = [&](int c, int s) {
        int sn = s ^ 1;
        int cn = c + 1;
        bool more = (cn < NCH);
        if (more) {
            if ((cn & 3) == 0) calc_off(cn >> 2);
            stage_B(cn, sn);
        }
        CP_COMMIT();
        if (more) gather4(cn, 0);
        mma_steps(s, 0);
        if (more) { convert4(sn, 0); gather4(cn, 4); }
        mma_steps(s, 2);
        if (more) convert4(sn, 4);
        CP_WAIT0();
        __syncthreads();
    };

    // ---- prologue: chunk 0 ----
    calc_off(0);
    stage_B(0, 0); CP_COMMIT();
    gather4(0, 0); convert4(0, 0);
    gather4(0, 4); convert4(0, 4);
    CP_WAIT0();
    __syncthreads();

    // ---- mainloop (unrolled x2: stage index is a literal) ----
    for (int c0 = 0; c0 < NCH; c0 += 2) {
        chunk_body(c0, 0);
        chunk_body(c0 + 1, 1);
    }

    // ---- epilogue: acc[m][n] -> out[b][n][pt*64 + m] ----
    float* ob = out + (size_t)b * CO_ * HW_ + (size_t)pt * BM;
    int mrow = l >> 2;
    int ncol = wn * 32 + ((l & 3) << 1);
    #pragma unroll
    for (int mi = 0; mi < 4; mi++) {
        #pragma unroll
        for (int ni = 0; ni < 4; ni++) {
            int m = mrow + mi * 16;
            int n = ncol + ni * 8;
            ob[(size_t)n * HW_ + m]           = acc[mi][ni][0];
            ob[(size_t)(n + 1) * HW_ + m]     = acc[mi][ni][1];
            ob[(size_t)n * HW_ + m + 8]       = acc[mi][ni][2];
            ob[(size_t)(n + 1) * HW_ + m + 8] = acc[mi][ni][3];
        }
    }
}

// ---------------------------------------------------------------------------
extern "C" void kernel_launch(void* const* d_in, const int* in_sizes, int n_in,
                              void* d_out, int out_size)
{
    const float* x   = (const float*)d_in[0];   // [4,256,64,64]
    const float* off = (const float*)d_in[1];   // [4,18,64,64]
    const float* wt  = (const float*)d_in[2];   // [256,256,3,3]
    float* out = (float*)d_out;                 // [4,256,64,64]

    cudaFuncSetAttribute(fused_kernel,
                         cudaFuncAttributeMaxDynamicSharedMemorySize, SM_TOTAL);

    dim3 pgrid(HW_ / 32, CI_ / 32, B_ + 1);     // transpose planes + repack plane
    prep_kernel<<<pgrid, 256>>>(x, wt);

    dim3 grid(HW_ / BM, B_);                    // 64 x 4 = 256 CTAs
    fused_kernel<<<grid, 256, SM_TOTAL>>>(off, out);
}